// round 1
// baseline (speedup 1.0000x reference)
#include <cuda_runtime.h>
#include <math.h>

#define NVAR 30000
#define NCLS 60000
#define DIM 256
#define NHEAD 8
#define HDIM 32

// ---------------- scratch layout (floats) ----------------
#define OFF_QV    0ull                     // 30000*256
#define OFF_KVV   7680000ull               // 30000*512
#define OFF_QC    23040000ull              // 60000*256
#define OFF_KVC   38400000ull              // 60000*512
#define OFF_NUMV  69120000ull              // 30000*256
#define OFF_NUMC  76800000ull              // 60000*256
#define OFF_DENV  92160000ull              // 30000*8
#define OFF_DENC  92400000ull              // 60000*8
#define OFF_ATTV  92880000ull              // 30000*256
#define OFF_ATTC  100560000ull             // 60000*256
#define OFF_V1    115920000ull             // 30000*256
#define OFF_C1    123600000ull             // 60000*256
#define OFF_HID   138960000ull             // 60000*256 (reused v then c)
#define OFF_TMP   154320000ull             // 60000*256
#define SCRATCH_TOTAL 169680000ull

__device__ float g_scratch[SCRATCH_TOTAL];

// ---------------- zero ----------------
__global__ void zero_kernel(float* __restrict__ p, size_t n) {
    size_t i = (size_t)blockIdx.x * blockDim.x + threadIdx.x;
    if (i < n) p[i] = 0.0f;
}

// ---------------- GEMM: C[N,M] = A[N,256] @ W[256,M] + bias, optional exact GELU ----------------
__global__ __launch_bounds__(256) void gemm256(
    const float* __restrict__ A, const float* __restrict__ W,
    const float* __restrict__ bias, float* __restrict__ C,
    int N, int M, int epi)
{
    __shared__ float As[16][64];
    __shared__ float Ws[16][68];

    int bm = blockIdx.y * 64;
    int bn = blockIdx.x * 64;
    int tid = threadIdx.x;
    int tx = tid & 15;
    int ty = tid >> 4;

    float acc[4][4];
    #pragma unroll
    for (int i = 0; i < 4; i++)
        #pragma unroll
        for (int j = 0; j < 4; j++) acc[i][j] = 0.0f;

    for (int k0 = 0; k0 < 256; k0 += 16) {
        #pragma unroll
        for (int i = 0; i < 4; i++) {
            int idx = tid + i * 256;
            int m = idx >> 4;
            int k = idx & 15;
            int gr = bm + m;
            As[k][m] = (gr < N) ? A[(size_t)gr * 256 + k0 + k] : 0.0f;
        }
        #pragma unroll
        for (int i = 0; i < 4; i++) {
            int idx = tid + i * 256;
            int k = idx >> 6;
            int cc = idx & 63;
            int gc = bn + cc;
            Ws[k][cc] = (gc < M) ? W[(size_t)(k0 + k) * M + gc] : 0.0f;
        }
        __syncthreads();
        #pragma unroll
        for (int k = 0; k < 16; k++) {
            float a[4], b[4];
            #pragma unroll
            for (int i = 0; i < 4; i++) a[i] = As[k][ty * 4 + i];
            #pragma unroll
            for (int j = 0; j < 4; j++) b[j] = Ws[k][tx * 4 + j];
            #pragma unroll
            for (int i = 0; i < 4; i++)
                #pragma unroll
                for (int j = 0; j < 4; j++)
                    acc[i][j] += a[i] * b[j];
        }
        __syncthreads();
    }

    #pragma unroll
    for (int i = 0; i < 4; i++) {
        int r = bm + ty * 4 + i;
        if (r >= N) continue;
        #pragma unroll
        for (int j = 0; j < 4; j++) {
            int cidx = bn + tx * 4 + j;
            if (cidx >= M) continue;
            float x = acc[i][j] + bias[cidx];
            if (epi == 1) x = 0.5f * x * (1.0f + erff(x * 0.70710678118654752f));
            C[(size_t)r * M + cidx] = x;
        }
    }
}

// ---------------- edge attention: one warp per edge ----------------
// num[seg,256] += e_h * val[src, h*32+c] ; den[seg,8] += e_h
__global__ void edge_attn(
    const float* __restrict__ Q, const float* __restrict__ KV,
    const int* __restrict__ eq, const int* __restrict__ ek,
    int nE, float* __restrict__ num, float* __restrict__ den)
{
    int warp = (int)(((size_t)blockIdx.x * blockDim.x + threadIdx.x) >> 5);
    int lane = threadIdx.x & 31;
    if (warp >= nE) return;
    int s = eq[warp];
    int t = ek[warp];
    const float* qrow = Q + (size_t)s * 256;
    const float* krow = KV + (size_t)t * 512;
    const float* vrow = krow + 256;

    float e[NHEAD];
    #pragma unroll
    for (int h = 0; h < NHEAD; h++) {
        float p = qrow[h * 32 + lane] * krow[h * 32 + lane];
        #pragma unroll
        for (int o = 16; o > 0; o >>= 1) p += __shfl_xor_sync(0xffffffffu, p, o);
        e[h] = __expf(p * 0.17677669529663687f);  // 1/sqrt(32)
    }
    // note: exp without max-subtraction is exact-equivalent softmax; |qk| < ~1 here
    if (lane < NHEAD) atomicAdd(&den[(size_t)s * NHEAD + lane], e[lane]);
    #pragma unroll
    for (int h = 0; h < NHEAD; h++) {
        atomicAdd(&num[(size_t)s * 256 + h * 32 + lane], e[h] * vrow[h * 32 + lane]);
    }
}

// ---------------- acc += num/den ----------------
__global__ void norm_add(float* __restrict__ acc, const float* __restrict__ num,
                         const float* __restrict__ den, int n)
{
    size_t i = (size_t)blockIdx.x * blockDim.x + threadIdx.x;
    if (i >= (size_t)n * 256) return;
    size_t row = i >> 8;
    int h = ((int)(i & 255)) >> 5;
    float d = den[row * NHEAD + h];
    acc[i] += (d > 0.0f) ? num[i] / d : 0.0f;
}

// ---------------- y = LN(x + a) ; one warp per row ----------------
__global__ void ln_add(const float* __restrict__ x, const float* __restrict__ a,
                       const float* __restrict__ g, const float* __restrict__ b,
                       float* __restrict__ y, int n)
{
    int row = blockIdx.x * (blockDim.x >> 5) + (threadIdx.x >> 5);
    int lane = threadIdx.x & 31;
    if (row >= n) return;
    float vals[8];
    float s = 0.0f;
    #pragma unroll
    for (int i = 0; i < 8; i++) {
        vals[i] = x[(size_t)row * 256 + i * 32 + lane] + a[(size_t)row * 256 + i * 32 + lane];
        s += vals[i];
    }
    #pragma unroll
    for (int o = 16; o > 0; o >>= 1) s += __shfl_xor_sync(0xffffffffu, s, o);
    float mean = s * (1.0f / 256.0f);
    float v2 = 0.0f;
    #pragma unroll
    for (int i = 0; i < 8; i++) { float d = vals[i] - mean; v2 += d * d; }
    #pragma unroll
    for (int o = 16; o > 0; o >>= 1) v2 += __shfl_xor_sync(0xffffffffu, v2, o);
    float rstd = rsqrtf(v2 * (1.0f / 256.0f) + 1e-5f);
    #pragma unroll
    for (int i = 0; i < 8; i++) {
        int cidx = i * 32 + lane;
        y[(size_t)row * 256 + cidx] = (vals[i] - mean) * rstd * g[cidx] + b[cidx];
    }
}

// ---------------- launch ----------------
static inline void launch_zero(float* p, size_t n) {
    int threads = 256;
    int blocks = (int)((n + threads - 1) / threads);
    zero_kernel<<<blocks, threads>>>(p, n);
}

static inline void launch_gemm(const float* A, const float* W, const float* bias,
                               float* C, int N, int M, int epi) {
    dim3 grid(M / 64, (N + 63) / 64);
    gemm256<<<grid, 256>>>(A, W, bias, C, N, M, epi);
}

extern "C" void kernel_launch(void* const* d_in, const int* in_sizes, int n_in,
                              void* d_out, int out_size)
{
    const float* v       = (const float*)d_in[0];
    const float* c       = (const float*)d_in[1];
    const int*   adj_pos = (const int*)d_in[2];
    const int*   adj_neg = (const int*)d_in[3];
    const float* Wq      = (const float*)d_in[4];
    const float* bq      = (const float*)d_in[5];
    const float* Wkv     = (const float*)d_in[6];
    const float* bkv     = (const float*)d_in[7];
    const float* fvw1    = (const float*)d_in[8];
    const float* fvb1    = (const float*)d_in[9];
    const float* fvw2    = (const float*)d_in[10];
    const float* fvb2    = (const float*)d_in[11];
    const float* fcw1    = (const float*)d_in[12];
    const float* fcb1    = (const float*)d_in[13];
    const float* fcw2    = (const float*)d_in[14];
    const float* fcb2    = (const float*)d_in[15];
    const float* lavg    = (const float*)d_in[16];
    const float* lavb    = (const float*)d_in[17];
    const float* lfvg    = (const float*)d_in[18];
    const float* lfvb    = (const float*)d_in[19];
    const float* lacg    = (const float*)d_in[20];
    const float* lacb    = (const float*)d_in[21];
    const float* lfcg    = (const float*)d_in[22];
    const float* lfcb    = (const float*)d_in[23];

    int E = in_sizes[2] / 2;

    float* buf;
    cudaGetSymbolAddress((void**)&buf, g_scratch);

    float* qv   = buf + OFF_QV;
    float* kvv  = buf + OFF_KVV;
    float* qc   = buf + OFF_QC;
    float* kvc  = buf + OFF_KVC;
    float* numV = buf + OFF_NUMV;
    float* numC = buf + OFF_NUMC;
    float* denV = buf + OFF_DENV;
    float* denC = buf + OFF_DENC;
    float* attV = buf + OFF_ATTV;
    float* attC = buf + OFF_ATTC;
    float* v1   = buf + OFF_V1;
    float* c1   = buf + OFF_C1;
    float* hid  = buf + OFF_HID;
    float* tmp  = buf + OFF_TMP;

    float* out_v = (float*)d_out;
    float* out_c = out_v + (size_t)NVAR * DIM;

    // projections
    launch_gemm(v, Wq, bq, qv, NVAR, 256, 0);
    launch_gemm(v, Wkv, bkv, kvv, NVAR, 512, 0);
    launch_gemm(c, Wq, bq, qc, NCLS, 256, 0);
    launch_gemm(c, Wkv, bkv, kvc, NCLS, 512, 0);

    launch_zero(attV, (size_t)NVAR * 256);
    launch_zero(attC, (size_t)NCLS * 256);

    int eblocks = (E * 32 + 255) / 256;

    // adj row0 = clause index, row1 = variable index
    const int* adjs[2] = { adj_pos, adj_neg };
    for (int p = 0; p < 2; p++) {
        const int* ec = adjs[p];        // clause indices
        const int* ev = adjs[p] + E;    // variable indices

        // v-side: q = qv[ev], k/val from c (kvc[ec]); segments = ev
        launch_zero(numV, (size_t)NVAR * 256);
        launch_zero(denV, (size_t)NVAR * NHEAD);
        edge_attn<<<eblocks, 256>>>(qv, kvc, ev, ec, E, numV, denV);
        norm_add<<<(int)(((size_t)NVAR * 256 + 255) / 256), 256>>>(attV, numV, denV, NVAR);

        // c-side: q = qc[ec], k/val from v (kvv[ev]); segments = ec
        launch_zero(numC, (size_t)NCLS * 256);
        launch_zero(denC, (size_t)NCLS * NHEAD);
        edge_attn<<<eblocks, 256>>>(qc, kvv, ec, ev, E, numC, denC);
        norm_add<<<(int)(((size_t)NCLS * 256 + 255) / 256), 256>>>(attC, numC, denC, NCLS);
    }

    // attention residual + LN
    ln_add<<<(NVAR + 7) / 8, 256>>>(v, attV, lavg, lavb, v1, NVAR);
    ln_add<<<(NCLS + 7) / 8, 256>>>(c, attC, lacg, lacb, c1, NCLS);

    // FFN v
    launch_gemm(v1, fvw1, fvb1, hid, NVAR, 256, 1);
    launch_gemm(hid, fvw2, fvb2, tmp, NVAR, 256, 0);
    ln_add<<<(NVAR + 7) / 8, 256>>>(v1, tmp, lfvg, lfvb, out_v, NVAR);

    // FFN c
    launch_gemm(c1, fcw1, fcb1, hid, NCLS, 256, 1);
    launch_gemm(hid, fcw2, fcb2, tmp, NCLS, 256, 0);
    ln_add<<<(NCLS + 7) / 8, 256>>>(c1, tmp, lfcg, lfcb, out_c, NCLS);
}

// round 2
// speedup vs baseline: 1.5364x; 1.5364x over previous
#include <cuda_runtime.h>
#include <math.h>

#define NVAR 30000
#define NCLS 60000
#define DIM 256
#define NHEAD 8

// ---------------- scratch layout (floats) ----------------
#define OFF_QV     0ull            // 30000*256
#define OFF_KVV    7680000ull      // 30000*512
#define OFF_QC     23040000ull     // 60000*256
#define OFF_KVC    38400000ull     // 60000*512
#define OFF_NUMVP  69120000ull     // 30000*256
#define OFF_NUMVN  76800000ull     // 30000*256
#define OFF_NUMCP  84480000ull     // 60000*256
#define OFF_NUMCN  99840000ull     // 60000*256
#define OFF_DENVP  115200000ull    // 30000*8
#define OFF_DENVN  115440000ull    // 30000*8
#define OFF_DENCP  115680000ull    // 60000*8
#define OFF_DENCN  116160000ull    // 60000*8
#define OFF_V1     116640000ull    // 30000*256
#define OFF_C1     124320000ull    // 60000*256
#define OFF_HID    139680000ull    // 60000*256
#define OFF_TMP    155040000ull    // 60000*256
#define SCRATCH_TOTAL 170400000ull

__device__ float g_scratch[SCRATCH_TOTAL];

// ---------------- SGEMM: C[N,M] = A[N,256] @ W[256,M] + bias (+ exact GELU) ----------------
// 128x128 tile, 8x8 per thread, float4 everywhere.
__global__ __launch_bounds__(256) void sgemm(
    const float* __restrict__ A, const float* __restrict__ W,
    const float* __restrict__ bias, float* __restrict__ C,
    int N, int M, int epi)
{
    __shared__ float As[16][128];
    __shared__ float Ws[16][128];

    int bm = blockIdx.y * 128;
    int bn = blockIdx.x * 128;
    int tid = threadIdx.x;
    int tx = tid & 15;   // col group 0..15
    int ty = tid >> 4;   // row group 0..15

    float acc[8][8];
    #pragma unroll
    for (int i = 0; i < 8; i++)
        #pragma unroll
        for (int j = 0; j < 8; j++) acc[i][j] = 0.0f;

    int arow0 = tid >> 2;   // 0..63
    int ac4   = tid & 3;    // float4 index within 16-wide k slab
    int wrow0 = tid >> 5;   // 0..7
    int wc4   = tid & 31;   // float4 index within 128-wide n slab

    for (int k0 = 0; k0 < 256; k0 += 16) {
        #pragma unroll
        for (int i = 0; i < 2; i++) {
            int r = arow0 + i * 64;
            int gr = bm + r;
            float4 av = make_float4(0.f, 0.f, 0.f, 0.f);
            if (gr < N) av = *(const float4*)&A[(size_t)gr * 256 + k0 + ac4 * 4];
            As[ac4 * 4 + 0][r] = av.x;
            As[ac4 * 4 + 1][r] = av.y;
            As[ac4 * 4 + 2][r] = av.z;
            As[ac4 * 4 + 3][r] = av.w;
        }
        #pragma unroll
        for (int i = 0; i < 2; i++) {
            int r = wrow0 + i * 8;
            *(float4*)&Ws[r][wc4 * 4] =
                *(const float4*)&W[(size_t)(k0 + r) * M + bn + wc4 * 4];
        }
        __syncthreads();
        #pragma unroll
        for (int k = 0; k < 16; k++) {
            float a[8], b[8];
            *(float4*)&a[0] = *(float4*)&As[k][ty * 8];
            *(float4*)&a[4] = *(float4*)&As[k][ty * 8 + 4];
            *(float4*)&b[0] = *(float4*)&Ws[k][tx * 8];
            *(float4*)&b[4] = *(float4*)&Ws[k][tx * 8 + 4];
            #pragma unroll
            for (int i = 0; i < 8; i++)
                #pragma unroll
                for (int j = 0; j < 8; j++)
                    acc[i][j] += a[i] * b[j];
        }
        __syncthreads();
    }

    #pragma unroll
    for (int i = 0; i < 8; i++) {
        int r = bm + ty * 8 + i;
        if (r >= N) continue;
        #pragma unroll
        for (int j4 = 0; j4 < 2; j4++) {
            int cidx = bn + tx * 8 + j4 * 4;
            float4 o;
            o.x = acc[i][j4 * 4 + 0] + bias[cidx + 0];
            o.y = acc[i][j4 * 4 + 1] + bias[cidx + 1];
            o.z = acc[i][j4 * 4 + 2] + bias[cidx + 2];
            o.w = acc[i][j4 * 4 + 3] + bias[cidx + 3];
            if (epi == 1) {
                o.x = 0.5f * o.x * (1.0f + erff(o.x * 0.70710678118654752f));
                o.y = 0.5f * o.y * (1.0f + erff(o.y * 0.70710678118654752f));
                o.z = 0.5f * o.z * (1.0f + erff(o.z * 0.70710678118654752f));
                o.w = 0.5f * o.w * (1.0f + erff(o.w * 0.70710678118654752f));
            }
            *(float4*)&C[(size_t)r * M + cidx] = o;
        }
    }
}

// ---------------- edge attention: one warp per edge ----------------
__global__ void edge_attn(
    const float* __restrict__ Q, const float* __restrict__ KV,
    const int* __restrict__ eq, const int* __restrict__ ek,
    int nE, float* __restrict__ num, float* __restrict__ den)
{
    int warp = (int)(((size_t)blockIdx.x * blockDim.x + threadIdx.x) >> 5);
    int lane = threadIdx.x & 31;
    if (warp >= nE) return;
    int s = eq[warp];
    int t = ek[warp];
    const float* qrow = Q + (size_t)s * 256;
    const float* krow = KV + (size_t)t * 512;
    const float* vrow = krow + 256;

    float e[NHEAD];
    #pragma unroll
    for (int h = 0; h < NHEAD; h++) {
        float p = qrow[h * 32 + lane] * krow[h * 32 + lane];
        #pragma unroll
        for (int o = 16; o > 0; o >>= 1) p += __shfl_xor_sync(0xffffffffu, p, o);
        e[h] = __expf(p * 0.17677669529663687f);  // 1/sqrt(32)
    }
    if (lane < NHEAD) atomicAdd(&den[(size_t)s * NHEAD + lane], e[lane]);
    #pragma unroll
    for (int h = 0; h < NHEAD; h++) {
        atomicAdd(&num[(size_t)s * 256 + h * 32 + lane], e[h] * vrow[h * 32 + lane]);
    }
}

// ---------------- y = LN(x + num_p/den_p + num_n/den_n) ; one warp per row ----------------
__global__ void ln_att(const float* __restrict__ x,
                       const float* __restrict__ np_, const float* __restrict__ dp,
                       const float* __restrict__ nn_, const float* __restrict__ dn,
                       const float* __restrict__ g, const float* __restrict__ b,
                       float* __restrict__ y, int n)
{
    int row = blockIdx.x * (blockDim.x >> 5) + (threadIdx.x >> 5);
    int lane = threadIdx.x & 31;
    if (row >= n) return;
    float vals[8];
    float s = 0.0f;
    #pragma unroll
    for (int i = 0; i < 8; i++) {
        size_t idx = (size_t)row * 256 + i * 32 + lane;
        float a = x[idx];
        float dpi = dp[(size_t)row * NHEAD + i];
        float dni = dn[(size_t)row * NHEAD + i];
        if (dpi > 0.0f) a += np_[idx] / dpi;
        if (dni > 0.0f) a += nn_[idx] / dni;
        vals[i] = a;
        s += a;
    }
    #pragma unroll
    for (int o = 16; o > 0; o >>= 1) s += __shfl_xor_sync(0xffffffffu, s, o);
    float mean = s * (1.0f / 256.0f);
    float v2 = 0.0f;
    #pragma unroll
    for (int i = 0; i < 8; i++) { float d = vals[i] - mean; v2 += d * d; }
    #pragma unroll
    for (int o = 16; o > 0; o >>= 1) v2 += __shfl_xor_sync(0xffffffffu, v2, o);
    float rstd = rsqrtf(v2 * (1.0f / 256.0f) + 1e-5f);
    #pragma unroll
    for (int i = 0; i < 8; i++) {
        int cidx = i * 32 + lane;
        y[(size_t)row * 256 + cidx] = (vals[i] - mean) * rstd * g[cidx] + b[cidx];
    }
}

// ---------------- y = LN(x + a) ; one warp per row ----------------
__global__ void ln_add(const float* __restrict__ x, const float* __restrict__ a,
                       const float* __restrict__ g, const float* __restrict__ b,
                       float* __restrict__ y, int n)
{
    int row = blockIdx.x * (blockDim.x >> 5) + (threadIdx.x >> 5);
    int lane = threadIdx.x & 31;
    if (row >= n) return;
    float vals[8];
    float s = 0.0f;
    #pragma unroll
    for (int i = 0; i < 8; i++) {
        size_t idx = (size_t)row * 256 + i * 32 + lane;
        vals[i] = x[idx] + a[idx];
        s += vals[i];
    }
    #pragma unroll
    for (int o = 16; o > 0; o >>= 1) s += __shfl_xor_sync(0xffffffffu, s, o);
    float mean = s * (1.0f / 256.0f);
    float v2 = 0.0f;
    #pragma unroll
    for (int i = 0; i < 8; i++) { float d = vals[i] - mean; v2 += d * d; }
    #pragma unroll
    for (int o = 16; o > 0; o >>= 1) v2 += __shfl_xor_sync(0xffffffffu, v2, o);
    float rstd = rsqrtf(v2 * (1.0f / 256.0f) + 1e-5f);
    #pragma unroll
    for (int i = 0; i < 8; i++) {
        int cidx = i * 32 + lane;
        y[(size_t)row * 256 + cidx] = (vals[i] - mean) * rstd * g[cidx] + b[cidx];
    }
}

static inline void launch_gemm(const float* A, const float* W, const float* bias,
                               float* C, int N, int M, int epi) {
    dim3 grid(M / 128, (N + 127) / 128);
    sgemm<<<grid, 256>>>(A, W, bias, C, N, M, epi);
}

extern "C" void kernel_launch(void* const* d_in, const int* in_sizes, int n_in,
                              void* d_out, int out_size)
{
    const float* v       = (const float*)d_in[0];
    const float* c       = (const float*)d_in[1];
    const int*   adj_pos = (const int*)d_in[2];
    const int*   adj_neg = (const int*)d_in[3];
    const float* Wq      = (const float*)d_in[4];
    const float* bq      = (const float*)d_in[5];
    const float* Wkv     = (const float*)d_in[6];
    const float* bkv     = (const float*)d_in[7];
    const float* fvw1    = (const float*)d_in[8];
    const float* fvb1    = (const float*)d_in[9];
    const float* fvw2    = (const float*)d_in[10];
    const float* fvb2    = (const float*)d_in[11];
    const float* fcw1    = (const float*)d_in[12];
    const float* fcb1    = (const float*)d_in[13];
    const float* fcw2    = (const float*)d_in[14];
    const float* fcb2    = (const float*)d_in[15];
    const float* lavg    = (const float*)d_in[16];
    const float* lavb    = (const float*)d_in[17];
    const float* lfvg    = (const float*)d_in[18];
    const float* lfvb    = (const float*)d_in[19];
    const float* lacg    = (const float*)d_in[20];
    const float* lacb    = (const float*)d_in[21];
    const float* lfcg    = (const float*)d_in[22];
    const float* lfcb    = (const float*)d_in[23];

    int E = in_sizes[2] / 2;

    float* buf;
    cudaGetSymbolAddress((void**)&buf, g_scratch);

    float* qv    = buf + OFF_QV;
    float* kvv   = buf + OFF_KVV;
    float* qc    = buf + OFF_QC;
    float* kvc   = buf + OFF_KVC;
    float* numVp = buf + OFF_NUMVP;
    float* numVn = buf + OFF_NUMVN;
    float* numCp = buf + OFF_NUMCP;
    float* numCn = buf + OFF_NUMCN;
    float* denVp = buf + OFF_DENVP;
    float* denVn = buf + OFF_DENVN;
    float* denCp = buf + OFF_DENCP;
    float* denCn = buf + OFF_DENCN;
    float* v1    = buf + OFF_V1;
    float* c1    = buf + OFF_C1;
    float* hid   = buf + OFF_HID;
    float* tmp   = buf + OFF_TMP;

    float* out_v = (float*)d_out;
    float* out_c = out_v + (size_t)NVAR * DIM;

    // zero accumulation buffers (num + den, contiguous region)
    cudaMemsetAsync(numVp, 0, (size_t)(OFF_V1 - OFF_NUMVP) * sizeof(float), 0);

    // projections
    launch_gemm(v, Wq, bq, qv, NVAR, 256, 0);
    launch_gemm(v, Wkv, bkv, kvv, NVAR, 512, 0);
    launch_gemm(c, Wq, bq, qc, NCLS, 256, 0);
    launch_gemm(c, Wkv, bkv, kvc, NCLS, 512, 0);

    int eblocks = (E * 32 + 255) / 256;

    // adj row0 = clause index, row1 = variable index
    // pos polarity
    edge_attn<<<eblocks, 256>>>(qv, kvc, adj_pos + E, adj_pos, E, numVp, denVp);
    edge_attn<<<eblocks, 256>>>(qc, kvv, adj_pos, adj_pos + E, E, numCp, denCp);
    // neg polarity
    edge_attn<<<eblocks, 256>>>(qv, kvc, adj_neg + E, adj_neg, E, numVn, denVn);
    edge_attn<<<eblocks, 256>>>(qc, kvv, adj_neg, adj_neg + E, E, numCn, denCn);

    // attention residual + LN (fused normalization)
    ln_att<<<(NVAR + 7) / 8, 256>>>(v, numVp, denVp, numVn, denVn, lavg, lavb, v1, NVAR);
    ln_att<<<(NCLS + 7) / 8, 256>>>(c, numCp, denCp, numCn, denCn, lacg, lacb, c1, NCLS);

    // FFN v
    launch_gemm(v1, fvw1, fvb1, hid, NVAR, 256, 1);
    launch_gemm(hid, fvw2, fvb2, tmp, NVAR, 256, 0);
    ln_add<<<(NVAR + 7) / 8, 256>>>(v1, tmp, lfvg, lfvb, out_v, NVAR);

    // FFN c
    launch_gemm(c1, fcw1, fcb1, hid, NCLS, 256, 1);
    launch_gemm(hid, fcw2, fcb2, tmp, NCLS, 256, 0);
    ln_add<<<(NCLS + 7) / 8, 256>>>(c1, tmp, lfcg, lfcb, out_c, NCLS);
}

// round 3
// speedup vs baseline: 2.8295x; 1.8417x over previous
#include <cuda_runtime.h>
#include <math.h>
#include <stdint.h>

#define NVAR 30000
#define NCLS 60000
#define DIM 256
#define NHEAD 8

// ---------------- scratch layout (floats) ----------------
#define OFF_QV     0ull            // 30000*256
#define OFF_KVV    7680000ull      // 30000*512
#define OFF_QC     23040000ull     // 60000*256
#define OFF_KVC    38400000ull     // 60000*512
#define OFF_NUMVP  69120000ull     // 30000*256
#define OFF_NUMVN  76800000ull     // 30000*256
#define OFF_NUMCP  84480000ull     // 60000*256
#define OFF_NUMCN  99840000ull     // 60000*256
#define OFF_DENVP  115200000ull    // 30000*8
#define OFF_DENVN  115440000ull    // 30000*8
#define OFF_DENCP  115680000ull    // 60000*8
#define OFF_DENCN  116160000ull    // 60000*8
#define OFF_V1     116640000ull    // 30000*256
#define OFF_C1     124320000ull    // 60000*256
#define OFF_HID    139680000ull    // 60000*256
#define OFF_TMP    155040000ull    // 60000*256
#define SCRATCH_TOTAL 170400000ull

__device__ float g_scratch[SCRATCH_TOTAL];

// ---------------- tf32 helpers ----------------
__device__ __forceinline__ uint32_t cvt_tf32(float x) {
    uint32_t r;
    asm("cvt.rna.tf32.f32 %0, %1;" : "=r"(r) : "f"(x));
    return r;
}

__device__ __forceinline__ void mma_tf32(float* d, const uint32_t* a, const uint32_t* b) {
    asm volatile(
        "mma.sync.aligned.m16n8k8.row.col.f32.tf32.tf32.f32 "
        "{%0,%1,%2,%3}, {%4,%5,%6,%7}, {%8,%9}, {%0,%1,%2,%3};"
        : "+f"(d[0]), "+f"(d[1]), "+f"(d[2]), "+f"(d[3])
        : "r"(a[0]), "r"(a[1]), "r"(a[2]), "r"(a[3]),
          "r"(b[0]), "r"(b[1]));
}

// ---------------- tensor-core GEMM: C[N,M] = A[N,256] @ W[256,M] + bias (+GELU) ----------------
// 128x64 block tile, BK=32, 8 warps (4M x 2N), warp tile 32x32 via m16n8k8 tf32 MMA.
#define BM 128
#define BN 64
#define BK 32
#define ASTR 36
#define BSTR 72

__global__ __launch_bounds__(256) void tgemm(
    const float* __restrict__ A, const float* __restrict__ W,
    const float* __restrict__ bias, float* __restrict__ C,
    int N, int M, int epi)
{
    __shared__ float As[BM * ASTR];   // [m][k], stride 36 (conflict-free frag loads)
    __shared__ float Ws[BK * BSTR];   // [k][n], stride 72

    int tid = threadIdx.x;
    int lane = tid & 31;
    int warp = tid >> 5;
    int wm = (warp & 3) * 32;
    int wn = (warp >> 2) * 32;
    int bm = blockIdx.y * BM;
    int bn = blockIdx.x * BN;

    int ak = (tid & 7) * 4;     // A: k-offset of this thread's float4
    int bnq = (tid & 15) * 4;   // B: n-offset of this thread's float4

    float4 pa[4], pb[2];

    float acc[2][4][4];
    #pragma unroll
    for (int mt = 0; mt < 2; mt++)
        #pragma unroll
        for (int nt = 0; nt < 4; nt++)
            #pragma unroll
            for (int i = 0; i < 4; i++) acc[mt][nt][i] = 0.0f;

    // ---- load slab 0 ----
    #pragma unroll
    for (int i = 0; i < 4; i++) {
        int m = (tid >> 3) + i * 32;
        int gr = bm + m;
        pa[i] = (gr < N) ? *(const float4*)&A[(size_t)gr * 256 + ak]
                         : make_float4(0.f, 0.f, 0.f, 0.f);
    }
    #pragma unroll
    for (int i = 0; i < 2; i++) {
        int k = (tid >> 4) + i * 16;
        pb[i] = *(const float4*)&W[(size_t)k * M + bn + bnq];
    }
    #pragma unroll
    for (int i = 0; i < 4; i++)
        *(float4*)&As[((tid >> 3) + i * 32) * ASTR + ak] = pa[i];
    #pragma unroll
    for (int i = 0; i < 2; i++)
        *(float4*)&Ws[((tid >> 4) + i * 16) * BSTR + bnq] = pb[i];
    __syncthreads();

    for (int s = 0; s < 8; s++) {
        // prefetch next slab into registers
        if (s < 7) {
            int k0 = (s + 1) * BK;
            #pragma unroll
            for (int i = 0; i < 4; i++) {
                int m = (tid >> 3) + i * 32;
                int gr = bm + m;
                pa[i] = (gr < N) ? *(const float4*)&A[(size_t)gr * 256 + k0 + ak]
                                 : make_float4(0.f, 0.f, 0.f, 0.f);
            }
            #pragma unroll
            for (int i = 0; i < 2; i++) {
                int k = (tid >> 4) + i * 16;
                pb[i] = *(const float4*)&W[(size_t)(k0 + k) * M + bn + bnq];
            }
        }

        // compute this slab: 4 k-steps of 8
        #pragma unroll
        for (int ks = 0; ks < 4; ks++) {
            int kb = ks * 8;
            uint32_t af[2][4], bf[4][2];
            #pragma unroll
            for (int mt = 0; mt < 2; mt++) {
                int mrow = wm + mt * 16 + (lane >> 2);
                int kc = kb + (lane & 3);
                af[mt][0] = cvt_tf32(As[mrow * ASTR + kc]);
                af[mt][1] = cvt_tf32(As[(mrow + 8) * ASTR + kc]);
                af[mt][2] = cvt_tf32(As[mrow * ASTR + kc + 4]);
                af[mt][3] = cvt_tf32(As[(mrow + 8) * ASTR + kc + 4]);
            }
            #pragma unroll
            for (int nt = 0; nt < 4; nt++) {
                int ncol = wn + nt * 8 + (lane >> 2);
                int kc = kb + (lane & 3);
                bf[nt][0] = cvt_tf32(Ws[kc * BSTR + ncol]);
                bf[nt][1] = cvt_tf32(Ws[(kc + 4) * BSTR + ncol]);
            }
            #pragma unroll
            for (int mt = 0; mt < 2; mt++)
                #pragma unroll
                for (int nt = 0; nt < 4; nt++)
                    mma_tf32(acc[mt][nt], af[mt], bf[nt]);
        }

        __syncthreads();
        if (s < 7) {
            #pragma unroll
            for (int i = 0; i < 4; i++)
                *(float4*)&As[((tid >> 3) + i * 32) * ASTR + ak] = pa[i];
            #pragma unroll
            for (int i = 0; i < 2; i++)
                *(float4*)&Ws[((tid >> 4) + i * 16) * BSTR + bnq] = pb[i];
            __syncthreads();
        }
    }

    // ---- epilogue ----
    #pragma unroll
    for (int mt = 0; mt < 2; mt++) {
        int r0 = bm + wm + mt * 16 + (lane >> 2);
        #pragma unroll
        for (int nt = 0; nt < 4; nt++) {
            int cb = bn + wn + nt * 8 + (lane & 3) * 2;
            float b0 = bias[cb], b1 = bias[cb + 1];
            float2 lo = make_float2(acc[mt][nt][0] + b0, acc[mt][nt][1] + b1);
            float2 hi = make_float2(acc[mt][nt][2] + b0, acc[mt][nt][3] + b1);
            if (epi == 1) {
                lo.x = 0.5f * lo.x * (1.0f + erff(lo.x * 0.70710678118654752f));
                lo.y = 0.5f * lo.y * (1.0f + erff(lo.y * 0.70710678118654752f));
                hi.x = 0.5f * hi.x * (1.0f + erff(hi.x * 0.70710678118654752f));
                hi.y = 0.5f * hi.y * (1.0f + erff(hi.y * 0.70710678118654752f));
            }
            if (r0 < N)     *(float2*)&C[(size_t)r0 * M + cb] = lo;
            if (r0 + 8 < N) *(float2*)&C[(size_t)(r0 + 8) * M + cb] = hi;
        }
    }
}

// ---------------- edge attention: one warp per edge ----------------
__global__ void edge_attn(
    const float* __restrict__ Q, const float* __restrict__ KV,
    const int* __restrict__ eq, const int* __restrict__ ek,
    int nE, float* __restrict__ num, float* __restrict__ den)
{
    int warp = (int)(((size_t)blockIdx.x * blockDim.x + threadIdx.x) >> 5);
    int lane = threadIdx.x & 31;
    if (warp >= nE) return;
    int s = eq[warp];
    int t = ek[warp];
    const float* qrow = Q + (size_t)s * 256;
    const float* krow = KV + (size_t)t * 512;
    const float* vrow = krow + 256;

    float e[NHEAD];
    #pragma unroll
    for (int h = 0; h < NHEAD; h++) {
        float p = qrow[h * 32 + lane] * krow[h * 32 + lane];
        #pragma unroll
        for (int o = 16; o > 0; o >>= 1) p += __shfl_xor_sync(0xffffffffu, p, o);
        e[h] = __expf(p * 0.17677669529663687f);  // 1/sqrt(32)
    }
    if (lane < NHEAD) atomicAdd(&den[(size_t)s * NHEAD + lane], e[lane]);
    #pragma unroll
    for (int h = 0; h < NHEAD; h++) {
        atomicAdd(&num[(size_t)s * 256 + h * 32 + lane], e[h] * vrow[h * 32 + lane]);
    }
}

// ---------------- y = LN(x + num_p/den_p + num_n/den_n) ----------------
__global__ void ln_att(const float* __restrict__ x,
                       const float* __restrict__ np_, const float* __restrict__ dp,
                       const float* __restrict__ nn_, const float* __restrict__ dn,
                       const float* __restrict__ g, const float* __restrict__ b,
                       float* __restrict__ y, int n)
{
    int row = blockIdx.x * (blockDim.x >> 5) + (threadIdx.x >> 5);
    int lane = threadIdx.x & 31;
    if (row >= n) return;
    float vals[8];
    float s = 0.0f;
    #pragma unroll
    for (int i = 0; i < 8; i++) {
        size_t idx = (size_t)row * 256 + i * 32 + lane;
        float a = x[idx];
        float dpi = dp[(size_t)row * NHEAD + i];
        float dni = dn[(size_t)row * NHEAD + i];
        if (dpi > 0.0f) a += np_[idx] / dpi;
        if (dni > 0.0f) a += nn_[idx] / dni;
        vals[i] = a;
        s += a;
    }
    #pragma unroll
    for (int o = 16; o > 0; o >>= 1) s += __shfl_xor_sync(0xffffffffu, s, o);
    float mean = s * (1.0f / 256.0f);
    float v2 = 0.0f;
    #pragma unroll
    for (int i = 0; i < 8; i++) { float d = vals[i] - mean; v2 += d * d; }
    #pragma unroll
    for (int o = 16; o > 0; o >>= 1) v2 += __shfl_xor_sync(0xffffffffu, v2, o);
    float rstd = rsqrtf(v2 * (1.0f / 256.0f) + 1e-5f);
    #pragma unroll
    for (int i = 0; i < 8; i++) {
        int cidx = i * 32 + lane;
        y[(size_t)row * 256 + cidx] = (vals[i] - mean) * rstd * g[cidx] + b[cidx];
    }
}

// ---------------- y = LN(x + a) ----------------
__global__ void ln_add(const float* __restrict__ x, const float* __restrict__ a,
                       const float* __restrict__ g, const float* __restrict__ b,
                       float* __restrict__ y, int n)
{
    int row = blockIdx.x * (blockDim.x >> 5) + (threadIdx.x >> 5);
    int lane = threadIdx.x & 31;
    if (row >= n) return;
    float vals[8];
    float s = 0.0f;
    #pragma unroll
    for (int i = 0; i < 8; i++) {
        size_t idx = (size_t)row * 256 + i * 32 + lane;
        vals[i] = x[idx] + a[idx];
        s += vals[i];
    }
    #pragma unroll
    for (int o = 16; o > 0; o >>= 1) s += __shfl_xor_sync(0xffffffffu, s, o);
    float mean = s * (1.0f / 256.0f);
    float v2 = 0.0f;
    #pragma unroll
    for (int i = 0; i < 8; i++) { float d = vals[i] - mean; v2 += d * d; }
    #pragma unroll
    for (int o = 16; o > 0; o >>= 1) v2 += __shfl_xor_sync(0xffffffffu, v2, o);
    float rstd = rsqrtf(v2 * (1.0f / 256.0f) + 1e-5f);
    #pragma unroll
    for (int i = 0; i < 8; i++) {
        int cidx = i * 32 + lane;
        y[(size_t)row * 256 + cidx] = (vals[i] - mean) * rstd * g[cidx] + b[cidx];
    }
}

static inline void launch_gemm(const float* A, const float* W, const float* bias,
                               float* C, int N, int M, int epi) {
    dim3 grid(M / BN, (N + BM - 1) / BM);
    tgemm<<<grid, 256>>>(A, W, bias, C, N, M, epi);
}

extern "C" void kernel_launch(void* const* d_in, const int* in_sizes, int n_in,
                              void* d_out, int out_size)
{
    const float* v       = (const float*)d_in[0];
    const float* c       = (const float*)d_in[1];
    const int*   adj_pos = (const int*)d_in[2];
    const int*   adj_neg = (const int*)d_in[3];
    const float* Wq      = (const float*)d_in[4];
    const float* bq      = (const float*)d_in[5];
    const float* Wkv     = (const float*)d_in[6];
    const float* bkv     = (const float*)d_in[7];
    const float* fvw1    = (const float*)d_in[8];
    const float* fvb1    = (const float*)d_in[9];
    const float* fvw2    = (const float*)d_in[10];
    const float* fvb2    = (const float*)d_in[11];
    const float* fcw1    = (const float*)d_in[12];
    const float* fcb1    = (const float*)d_in[13];
    const float* fcw2    = (const float*)d_in[14];
    const float* fcb2    = (const float*)d_in[15];
    const float* lavg    = (const float*)d_in[16];
    const float* lavb    = (const float*)d_in[17];
    const float* lfvg    = (const float*)d_in[18];
    const float* lfvb    = (const float*)d_in[19];
    const float* lacg    = (const float*)d_in[20];
    const float* lacb    = (const float*)d_in[21];
    const float* lfcg    = (const float*)d_in[22];
    const float* lfcb    = (const float*)d_in[23];

    int E = in_sizes[2] / 2;

    float* buf;
    cudaGetSymbolAddress((void**)&buf, g_scratch);

    float* qv    = buf + OFF_QV;
    float* kvv   = buf + OFF_KVV;
    float* qc    = buf + OFF_QC;
    float* kvc   = buf + OFF_KVC;
    float* numVp = buf + OFF_NUMVP;
    float* numVn = buf + OFF_NUMVN;
    float* numCp = buf + OFF_NUMCP;
    float* numCn = buf + OFF_NUMCN;
    float* denVp = buf + OFF_DENVP;
    float* denVn = buf + OFF_DENVN;
    float* denCp = buf + OFF_DENCP;
    float* denCn = buf + OFF_DENCN;
    float* v1    = buf + OFF_V1;
    float* c1    = buf + OFF_C1;
    float* hid   = buf + OFF_HID;
    float* tmp   = buf + OFF_TMP;

    float* out_v = (float*)d_out;
    float* out_c = out_v + (size_t)NVAR * DIM;

    // zero accumulation buffers (num + den, contiguous region)
    cudaMemsetAsync(numVp, 0, (size_t)(OFF_V1 - OFF_NUMVP) * sizeof(float), 0);

    // projections
    launch_gemm(v, Wq, bq, qv, NVAR, 256, 0);
    launch_gemm(v, Wkv, bkv, kvv, NVAR, 512, 0);
    launch_gemm(c, Wq, bq, qc, NCLS, 256, 0);
    launch_gemm(c, Wkv, bkv, kvc, NCLS, 512, 0);

    int eblocks = (E * 32 + 255) / 256;

    // adj row0 = clause index, row1 = variable index
    edge_attn<<<eblocks, 256>>>(qv, kvc, adj_pos + E, adj_pos, E, numVp, denVp);
    edge_attn<<<eblocks, 256>>>(qc, kvv, adj_pos, adj_pos + E, E, numCp, denCp);
    edge_attn<<<eblocks, 256>>>(qv, kvc, adj_neg + E, adj_neg, E, numVn, denVn);
    edge_attn<<<eblocks, 256>>>(qc, kvv, adj_neg, adj_neg + E, E, numCn, denCn);

    // attention residual + LN (fused normalization)
    ln_att<<<(NVAR + 7) / 8, 256>>>(v, numVp, denVp, numVn, denVn, lavg, lavb, v1, NVAR);
    ln_att<<<(NCLS + 7) / 8, 256>>>(c, numCp, denCp, numCn, denCn, lacg, lacb, c1, NCLS);

    // FFN v
    launch_gemm(v1, fvw1, fvb1, hid, NVAR, 256, 1);
    launch_gemm(hid, fvw2, fvb2, tmp, NVAR, 256, 0);
    ln_add<<<(NVAR + 7) / 8, 256>>>(v1, tmp, lfvg, lfvb, out_v, NVAR);

    // FFN c
    launch_gemm(c1, fcw1, fcb1, hid, NCLS, 256, 1);
    launch_gemm(hid, fcw2, fcb2, tmp, NCLS, 256, 0);
    ln_add<<<(NCLS + 7) / 8, 256>>>(c1, tmp, lfcg, lfcb, out_c, NCLS);
}

// round 4
// speedup vs baseline: 3.0834x; 1.0897x over previous
#include <cuda_runtime.h>
#include <math.h>
#include <stdint.h>

#define NVAR 30000
#define NCLS 60000
#define DIM 256
#define NHEAD 8

// ---------------- scratch layout (floats) ----------------
#define OFF_QV     0ull            // 30000*256
#define OFF_KVV    7680000ull      // 30000*512
#define OFF_QC     23040000ull     // 60000*256
#define OFF_KVC    38400000ull     // 60000*512
#define OFF_NUMVP  69120000ull     // 30000*256
#define OFF_NUMVN  76800000ull     // 30000*256
#define OFF_NUMCP  84480000ull     // 60000*256
#define OFF_NUMCN  99840000ull     // 60000*256
#define OFF_DENVP  115200000ull    // 30000*8
#define OFF_DENVN  115440000ull    // 30000*8
#define OFF_DENCP  115680000ull    // 60000*8
#define OFF_DENCN  116160000ull    // 60000*8
#define OFF_V1     116640000ull    // 30000*256
#define OFF_C1     124320000ull    // 60000*256
#define OFF_HID    139680000ull    // 60000*256
#define OFF_TMP    155040000ull    // 60000*256
#define SCRATCH_TOTAL 170400000ull

__device__ float g_scratch[SCRATCH_TOTAL];

// ---------------- tf32 helpers ----------------
__device__ __forceinline__ float cvt_tf32f(float x) {
    uint32_t r;
    asm("cvt.rna.tf32.f32 %0, %1;" : "=r"(r) : "f"(x));
    return __uint_as_float(r);
}

__device__ __forceinline__ void mma_tf32(float* d, const uint32_t* a, const uint32_t* b) {
    asm volatile(
        "mma.sync.aligned.m16n8k8.row.col.f32.tf32.tf32.f32 "
        "{%0,%1,%2,%3}, {%4,%5,%6,%7}, {%8,%9}, {%0,%1,%2,%3};"
        : "+f"(d[0]), "+f"(d[1]), "+f"(d[2]), "+f"(d[3])
        : "r"(a[0]), "r"(a[1]), "r"(a[2]), "r"(a[3]),
          "r"(b[0]), "r"(b[1]));
}

__device__ __forceinline__ void red_add_v4(float* addr, float4 v) {
    asm volatile("red.global.add.v4.f32 [%0], {%1,%2,%3,%4};"
                 :: "l"(addr), "f"(v.x), "f"(v.y), "f"(v.z), "f"(v.w) : "memory");
}

// ---------------- tensor-core GEMM: C[N,M] = A[N,256] @ W[256,M] + bias (+GELU) ----------------
// 128x64 block tile, BK=32, 8 warps (4M x 2N), warp tile 32x32 via m16n8k8 tf32 MMA.
// tf32 conversion happens once at smem-store time.
#define BM 128
#define BN 64
#define BK 32
#define ASTR 36
#define BSTR 72

__global__ __launch_bounds__(256) void tgemm(
    const float* __restrict__ A, const float* __restrict__ W,
    const float* __restrict__ bias, float* __restrict__ C,
    int N, int M, int epi)
{
    __shared__ float As[BM * ASTR];   // [m][k], tf32-bit values
    __shared__ float Ws[BK * BSTR];   // [k][n], tf32-bit values

    int tid = threadIdx.x;
    int lane = tid & 31;
    int warp = tid >> 5;
    int wm = (warp & 3) * 32;
    int wn = (warp >> 2) * 32;
    int bm = blockIdx.y * BM;
    int bn = blockIdx.x * BN;

    int ak = (tid & 7) * 4;
    int bnq = (tid & 15) * 4;

    float4 pa[4], pb[2];

    float acc[2][4][4];
    #pragma unroll
    for (int mt = 0; mt < 2; mt++)
        #pragma unroll
        for (int nt = 0; nt < 4; nt++)
            #pragma unroll
            for (int i = 0; i < 4; i++) acc[mt][nt][i] = 0.0f;

    // ---- load slab 0 ----
    #pragma unroll
    for (int i = 0; i < 4; i++) {
        int m = (tid >> 3) + i * 32;
        int gr = bm + m;
        pa[i] = (gr < N) ? *(const float4*)&A[(size_t)gr * 256 + ak]
                         : make_float4(0.f, 0.f, 0.f, 0.f);
    }
    #pragma unroll
    for (int i = 0; i < 2; i++) {
        int k = (tid >> 4) + i * 16;
        pb[i] = *(const float4*)&W[(size_t)k * M + bn + bnq];
    }
    #pragma unroll
    for (int i = 0; i < 4; i++) {
        float4 t = pa[i];
        t.x = cvt_tf32f(t.x); t.y = cvt_tf32f(t.y);
        t.z = cvt_tf32f(t.z); t.w = cvt_tf32f(t.w);
        *(float4*)&As[((tid >> 3) + i * 32) * ASTR + ak] = t;
    }
    #pragma unroll
    for (int i = 0; i < 2; i++) {
        float4 t = pb[i];
        t.x = cvt_tf32f(t.x); t.y = cvt_tf32f(t.y);
        t.z = cvt_tf32f(t.z); t.w = cvt_tf32f(t.w);
        *(float4*)&Ws[((tid >> 4) + i * 16) * BSTR + bnq] = t;
    }
    __syncthreads();

    for (int s = 0; s < 8; s++) {
        if (s < 7) {
            int k0 = (s + 1) * BK;
            #pragma unroll
            for (int i = 0; i < 4; i++) {
                int m = (tid >> 3) + i * 32;
                int gr = bm + m;
                pa[i] = (gr < N) ? *(const float4*)&A[(size_t)gr * 256 + k0 + ak]
                                 : make_float4(0.f, 0.f, 0.f, 0.f);
            }
            #pragma unroll
            for (int i = 0; i < 2; i++) {
                int k = (tid >> 4) + i * 16;
                pb[i] = *(const float4*)&W[(size_t)(k0 + k) * M + bn + bnq];
            }
        }

        #pragma unroll
        for (int ks = 0; ks < 4; ks++) {
            int kb = ks * 8;
            uint32_t af[2][4], bf[4][2];
            #pragma unroll
            for (int mt = 0; mt < 2; mt++) {
                int mrow = wm + mt * 16 + (lane >> 2);
                int kc = kb + (lane & 3);
                af[mt][0] = __float_as_uint(As[mrow * ASTR + kc]);
                af[mt][1] = __float_as_uint(As[(mrow + 8) * ASTR + kc]);
                af[mt][2] = __float_as_uint(As[mrow * ASTR + kc + 4]);
                af[mt][3] = __float_as_uint(As[(mrow + 8) * ASTR + kc + 4]);
            }
            #pragma unroll
            for (int nt = 0; nt < 4; nt++) {
                int ncol = wn + nt * 8 + (lane >> 2);
                int kc = kb + (lane & 3);
                bf[nt][0] = __float_as_uint(Ws[kc * BSTR + ncol]);
                bf[nt][1] = __float_as_uint(Ws[(kc + 4) * BSTR + ncol]);
            }
            #pragma unroll
            for (int mt = 0; mt < 2; mt++)
                #pragma unroll
                for (int nt = 0; nt < 4; nt++)
                    mma_tf32(acc[mt][nt], af[mt], bf[nt]);
        }

        __syncthreads();
        if (s < 7) {
            #pragma unroll
            for (int i = 0; i < 4; i++) {
                float4 t = pa[i];
                t.x = cvt_tf32f(t.x); t.y = cvt_tf32f(t.y);
                t.z = cvt_tf32f(t.z); t.w = cvt_tf32f(t.w);
                *(float4*)&As[((tid >> 3) + i * 32) * ASTR + ak] = t;
            }
            #pragma unroll
            for (int i = 0; i < 2; i++) {
                float4 t = pb[i];
                t.x = cvt_tf32f(t.x); t.y = cvt_tf32f(t.y);
                t.z = cvt_tf32f(t.z); t.w = cvt_tf32f(t.w);
                *(float4*)&Ws[((tid >> 4) + i * 16) * BSTR + bnq] = t;
            }
            __syncthreads();
        }
    }

    // ---- epilogue ----
    #pragma unroll
    for (int mt = 0; mt < 2; mt++) {
        int r0 = bm + wm + mt * 16 + (lane >> 2);
        #pragma unroll
        for (int nt = 0; nt < 4; nt++) {
            int cb = bn + wn + nt * 8 + (lane & 3) * 2;
            float b0 = bias[cb], b1 = bias[cb + 1];
            float2 lo = make_float2(acc[mt][nt][0] + b0, acc[mt][nt][1] + b1);
            float2 hi = make_float2(acc[mt][nt][2] + b0, acc[mt][nt][3] + b1);
            if (epi == 1) {
                lo.x = 0.5f * lo.x * (1.0f + erff(lo.x * 0.70710678118654752f));
                lo.y = 0.5f * lo.y * (1.0f + erff(lo.y * 0.70710678118654752f));
                hi.x = 0.5f * hi.x * (1.0f + erff(hi.x * 0.70710678118654752f));
                hi.y = 0.5f * hi.y * (1.0f + erff(hi.y * 0.70710678118654752f));
            }
            if (r0 < N)     *(float2*)&C[(size_t)r0 * M + cb] = lo;
            if (r0 + 8 < N) *(float2*)&C[(size_t)(r0 + 8) * M + cb] = hi;
        }
    }
}

// ---------------- edge attention: one warp per edge, float4 + red.v4 ----------------
// lane layout per 128-float chunk: head = chunk*4 + (lane>>3), dims = (lane&7)*4 .. +3
__global__ void edge_attn(
    const float* __restrict__ Q, const float* __restrict__ KV,
    const int* __restrict__ eq, const int* __restrict__ ek,
    int nE, float* __restrict__ num, float* __restrict__ den)
{
    int warp = (int)(((size_t)blockIdx.x * blockDim.x + threadIdx.x) >> 5);
    int lane = threadIdx.x & 31;
    if (warp >= nE) return;
    int s = eq[warp];
    int t = ek[warp];
    const float4* q4 = (const float4*)(Q + (size_t)s * 256);
    const float4* k4 = (const float4*)(KV + (size_t)t * 512);
    const float4* v4 = k4 + 64;

    float e[2];
    #pragma unroll
    for (int ch = 0; ch < 2; ch++) {
        float4 qq = q4[ch * 32 + lane];
        float4 kk = k4[ch * 32 + lane];
        float p = qq.x * kk.x + qq.y * kk.y + qq.z * kk.z + qq.w * kk.w;
        p += __shfl_xor_sync(0xffffffffu, p, 1);
        p += __shfl_xor_sync(0xffffffffu, p, 2);
        p += __shfl_xor_sync(0xffffffffu, p, 4);
        e[ch] = __expf(p * 0.17677669529663687f);  // 1/sqrt(32)
    }
    #pragma unroll
    for (int ch = 0; ch < 2; ch++) {
        if ((lane & 7) == 0)
            atomicAdd(&den[(size_t)s * NHEAD + ch * 4 + (lane >> 3)], e[ch]);
        float4 vv = v4[ch * 32 + lane];
        red_add_v4(&num[(size_t)s * 256 + ch * 128 + lane * 4],
                   make_float4(e[ch] * vv.x, e[ch] * vv.y, e[ch] * vv.z, e[ch] * vv.w));
    }
}

// ---------------- y = LN(x + num_p/den_p + num_n/den_n) ----------------
__global__ void ln_att(const float* __restrict__ x,
                       const float* __restrict__ np_, const float* __restrict__ dp,
                       const float* __restrict__ nn_, const float* __restrict__ dn,
                       const float* __restrict__ g, const float* __restrict__ b,
                       float* __restrict__ y, int n)
{
    int row = blockIdx.x * (blockDim.x >> 5) + (threadIdx.x >> 5);
    int lane = threadIdx.x & 31;
    if (row >= n) return;
    float vals[8];
    float s = 0.0f;
    #pragma unroll
    for (int i = 0; i < 8; i++) {
        size_t idx = (size_t)row * 256 + i * 32 + lane;
        float a = x[idx];
        float dpi = dp[(size_t)row * NHEAD + i];
        float dni = dn[(size_t)row * NHEAD + i];
        if (dpi > 0.0f) a += np_[idx] / dpi;
        if (dni > 0.0f) a += nn_[idx] / dni;
        vals[i] = a;
        s += a;
    }
    #pragma unroll
    for (int o = 16; o > 0; o >>= 1) s += __shfl_xor_sync(0xffffffffu, s, o);
    float mean = s * (1.0f / 256.0f);
    float v2 = 0.0f;
    #pragma unroll
    for (int i = 0; i < 8; i++) { float d = vals[i] - mean; v2 += d * d; }
    #pragma unroll
    for (int o = 16; o > 0; o >>= 1) v2 += __shfl_xor_sync(0xffffffffu, v2, o);
    float rstd = rsqrtf(v2 * (1.0f / 256.0f) + 1e-5f);
    #pragma unroll
    for (int i = 0; i < 8; i++) {
        int cidx = i * 32 + lane;
        y[(size_t)row * 256 + cidx] = (vals[i] - mean) * rstd * g[cidx] + b[cidx];
    }
}

// ---------------- y = LN(x + a) ----------------
__global__ void ln_add(const float* __restrict__ x, const float* __restrict__ a,
                       const float* __restrict__ g, const float* __restrict__ b,
                       float* __restrict__ y, int n)
{
    int row = blockIdx.x * (blockDim.x >> 5) + (threadIdx.x >> 5);
    int lane = threadIdx.x & 31;
    if (row >= n) return;
    float vals[8];
    float s = 0.0f;
    #pragma unroll
    for (int i = 0; i < 8; i++) {
        size_t idx = (size_t)row * 256 + i * 32 + lane;
        vals[i] = x[idx] + a[idx];
        s += vals[i];
    }
    #pragma unroll
    for (int o = 16; o > 0; o >>= 1) s += __shfl_xor_sync(0xffffffffu, s, o);
    float mean = s * (1.0f / 256.0f);
    float v2 = 0.0f;
    #pragma unroll
    for (int i = 0; i < 8; i++) { float d = vals[i] - mean; v2 += d * d; }
    #pragma unroll
    for (int o = 16; o > 0; o >>= 1) v2 += __shfl_xor_sync(0xffffffffu, v2, o);
    float rstd = rsqrtf(v2 * (1.0f / 256.0f) + 1e-5f);
    #pragma unroll
    for (int i = 0; i < 8; i++) {
        int cidx = i * 32 + lane;
        y[(size_t)row * 256 + cidx] = (vals[i] - mean) * rstd * g[cidx] + b[cidx];
    }
}

static inline void launch_gemm(const float* A, const float* W, const float* bias,
                               float* C, int N, int M, int epi) {
    dim3 grid(M / BN, (N + BM - 1) / BM);
    tgemm<<<grid, 256>>>(A, W, bias, C, N, M, epi);
}

extern "C" void kernel_launch(void* const* d_in, const int* in_sizes, int n_in,
                              void* d_out, int out_size)
{
    const float* v       = (const float*)d_in[0];
    const float* c       = (const float*)d_in[1];
    const int*   adj_pos = (const int*)d_in[2];
    const int*   adj_neg = (const int*)d_in[3];
    const float* Wq      = (const float*)d_in[4];
    const float* bq      = (const float*)d_in[5];
    const float* Wkv     = (const float*)d_in[6];
    const float* bkv     = (const float*)d_in[7];
    const float* fvw1    = (const float*)d_in[8];
    const float* fvb1    = (const float*)d_in[9];
    const float* fvw2    = (const float*)d_in[10];
    const float* fvb2    = (const float*)d_in[11];
    const float* fcw1    = (const float*)d_in[12];
    const float* fcb1    = (const float*)d_in[13];
    const float* fcw2    = (const float*)d_in[14];
    const float* fcb2    = (const float*)d_in[15];
    const float* lavg    = (const float*)d_in[16];
    const float* lavb    = (const float*)d_in[17];
    const float* lfvg    = (const float*)d_in[18];
    const float* lfvb    = (const float*)d_in[19];
    const float* lacg    = (const float*)d_in[20];
    const float* lacb    = (const float*)d_in[21];
    const float* lfcg    = (const float*)d_in[22];
    const float* lfcb    = (const float*)d_in[23];

    int E = in_sizes[2] / 2;

    float* buf;
    cudaGetSymbolAddress((void**)&buf, g_scratch);

    float* qv    = buf + OFF_QV;
    float* kvv   = buf + OFF_KVV;
    float* qc    = buf + OFF_QC;
    float* kvc   = buf + OFF_KVC;
    float* numVp = buf + OFF_NUMVP;
    float* numVn = buf + OFF_NUMVN;
    float* numCp = buf + OFF_NUMCP;
    float* numCn = buf + OFF_NUMCN;
    float* denVp = buf + OFF_DENVP;
    float* denVn = buf + OFF_DENVN;
    float* denCp = buf + OFF_DENCP;
    float* denCn = buf + OFF_DENCN;
    float* v1    = buf + OFF_V1;
    float* c1    = buf + OFF_C1;
    float* hid   = buf + OFF_HID;
    float* tmp   = buf + OFF_TMP;

    float* out_v = (float*)d_out;
    float* out_c = out_v + (size_t)NVAR * DIM;

    cudaMemsetAsync(numVp, 0, (size_t)(OFF_V1 - OFF_NUMVP) * sizeof(float), 0);

    launch_gemm(v, Wq, bq, qv, NVAR, 256, 0);
    launch_gemm(v, Wkv, bkv, kvv, NVAR, 512, 0);
    launch_gemm(c, Wq, bq, qc, NCLS, 256, 0);
    launch_gemm(c, Wkv, bkv, kvc, NCLS, 512, 0);

    int eblocks = (E * 32 + 255) / 256;

    edge_attn<<<eblocks, 256>>>(qv, kvc, adj_pos + E, adj_pos, E, numVp, denVp);
    edge_attn<<<eblocks, 256>>>(qc, kvv, adj_pos, adj_pos + E, E, numCp, denCp);
    edge_attn<<<eblocks, 256>>>(qv, kvc, adj_neg + E, adj_neg, E, numVn, denVn);
    edge_attn<<<eblocks, 256>>>(qc, kvv, adj_neg, adj_neg + E, E, numCn, denCn);

    ln_att<<<(NVAR + 7) / 8, 256>>>(v, numVp, denVp, numVn, denVn, lavg, lavb, v1, NVAR);
    ln_att<<<(NCLS + 7) / 8, 256>>>(c, numCp, denCp, numCn, denCn, lacg, lacb, c1, NCLS);

    launch_gemm(v1, fvw1, fvb1, hid, NVAR, 256, 1);
    launch_gemm(hid, fvw2, fvb2, tmp, NVAR, 256, 0);
    ln_add<<<(NVAR + 7) / 8, 256>>>(v1, tmp, lfvg, lfvb, out_v, NVAR);

    launch_gemm(c1, fcw1, fcb1, hid, NCLS, 256, 1);
    launch_gemm(hid, fcw2, fcb2, tmp, NCLS, 256, 0);
    ln_add<<<(NCLS + 7) / 8, 256>>>(c1, tmp, lfcg, lfcb, out_c, NCLS);
}

// round 5
// speedup vs baseline: 3.6910x; 1.1971x over previous
#include <cuda_runtime.h>
#include <cuda_bf16.h>
#include <math.h>
#include <stdint.h>

#define NVAR 30000
#define NCLS 60000
#define DIM 256
#define NHEAD 8

// ---------------- scratch layout (floats) ----------------
#define OFF_QV     0ull
#define OFF_KVV    7680000ull
#define OFF_QC     23040000ull
#define OFF_KVC    38400000ull
#define OFF_NUMVP  69120000ull
#define OFF_NUMVN  76800000ull
#define OFF_NUMCP  84480000ull
#define OFF_NUMCN  99840000ull
#define OFF_DENVP  115200000ull
#define OFF_DENVN  115440000ull
#define OFF_DENCP  115680000ull
#define OFF_DENCN  116160000ull
#define OFF_V1     116640000ull
#define OFF_C1     124320000ull
#define OFF_HID    139680000ull
#define OFF_TMP    155040000ull
#define SCRATCH_TOTAL 170400000ull

__device__ float g_scratch[SCRATCH_TOTAL];

// ---------------- helpers ----------------
__device__ __forceinline__ uint2 f4_to_bf8(float4 t) {
    __nv_bfloat162 lo = __float22bfloat162_rn(make_float2(t.x, t.y));
    __nv_bfloat162 hi = __float22bfloat162_rn(make_float2(t.z, t.w));
    uint2 r;
    r.x = *(uint32_t*)&lo;
    r.y = *(uint32_t*)&hi;
    return r;
}

__device__ __forceinline__ void ldsm_x4(uint32_t* r, uint32_t saddr) {
    asm volatile("ldmatrix.sync.aligned.m8n8.x4.shared.b16 {%0,%1,%2,%3}, [%4];"
                 : "=r"(r[0]), "=r"(r[1]), "=r"(r[2]), "=r"(r[3]) : "r"(saddr));
}
__device__ __forceinline__ void ldsm_x4_trans(uint32_t* r, uint32_t saddr) {
    asm volatile("ldmatrix.sync.aligned.m8n8.x4.trans.shared.b16 {%0,%1,%2,%3}, [%4];"
                 : "=r"(r[0]), "=r"(r[1]), "=r"(r[2]), "=r"(r[3]) : "r"(saddr));
}

__device__ __forceinline__ void mma_bf16(float* d, const uint32_t* a, const uint32_t* b) {
    asm volatile(
        "mma.sync.aligned.m16n8k16.row.col.f32.bf16.bf16.f32 "
        "{%0,%1,%2,%3}, {%4,%5,%6,%7}, {%8,%9}, {%0,%1,%2,%3};"
        : "+f"(d[0]), "+f"(d[1]), "+f"(d[2]), "+f"(d[3])
        : "r"(a[0]), "r"(a[1]), "r"(a[2]), "r"(a[3]),
          "r"(b[0]), "r"(b[1]));
}

__device__ __forceinline__ void red_add_v4(float* addr, float4 v) {
    asm volatile("red.global.add.v4.f32 [%0], {%1,%2,%3,%4};"
                 :: "l"(addr), "f"(v.x), "f"(v.y), "f"(v.z), "f"(v.w) : "memory");
}

// ---------------- bf16 tensor-core GEMM ----------------
// C[N,M] = A[N,256] @ W[256,M] + bias (+GELU)
// 128x64 block tile, BK=32, 8 warps (4M x 2N), warp tile 32x32, mma m16n8k16.
#define BM 128
#define BN 64
#define BK 32
#define ASTR 40   // bf16 stride, 16B-aligned rows, conflict-free LDSM
#define BSTR 72

__global__ __launch_bounds__(256) void tgemm(
    const float* __restrict__ A, const float* __restrict__ W,
    const float* __restrict__ bias, float* __restrict__ C,
    int N, int M, int epi)
{
    __shared__ __nv_bfloat16 As[BM * ASTR];
    __shared__ __nv_bfloat16 Ws[BK * BSTR];

    int tid = threadIdx.x;
    int lane = tid & 31;
    int warp = tid >> 5;
    int wm = (warp & 3) * 32;
    int wn = (warp >> 2) * 32;
    int bm = blockIdx.y * BM;
    int bn = blockIdx.x * BN;

    int ak = (tid & 7) * 4;     // A k-offset (float4 granule)
    int bnq = (tid & 15) * 4;   // W n-offset

    uint32_t as_base = (uint32_t)__cvta_generic_to_shared(As);
    uint32_t ws_base = (uint32_t)__cvta_generic_to_shared(Ws);

    float4 pa[4], pb[2];

    float acc[2][4][4];
    #pragma unroll
    for (int mt = 0; mt < 2; mt++)
        #pragma unroll
        for (int nt = 0; nt < 4; nt++)
            #pragma unroll
            for (int i = 0; i < 4; i++) acc[mt][nt][i] = 0.0f;

    // fragment LDSM addresses (fixed per thread, advance by k_base)
    // A: row = m_base + (lane&15), col = kb + (lane>>4)*8
    // B: row = kb + (lane&15),     col = n_base + (lane>>4)*8
    int a_r = lane & 15;
    int a_c = (lane >> 4) * 8;

    // ---- load slab 0 ----
    #pragma unroll
    for (int i = 0; i < 4; i++) {
        int m = (tid >> 3) + i * 32;
        int gr = bm + m;
        pa[i] = (gr < N) ? *(const float4*)&A[(size_t)gr * 256 + ak]
                         : make_float4(0.f, 0.f, 0.f, 0.f);
    }
    #pragma unroll
    for (int i = 0; i < 2; i++) {
        int k = (tid >> 4) + i * 16;
        pb[i] = *(const float4*)&W[(size_t)k * M + bn + bnq];
    }
    #pragma unroll
    for (int i = 0; i < 4; i++)
        *(uint2*)&As[((tid >> 3) + i * 32) * ASTR + ak] = f4_to_bf8(pa[i]);
    #pragma unroll
    for (int i = 0; i < 2; i++)
        *(uint2*)&Ws[((tid >> 4) + i * 16) * BSTR + bnq] = f4_to_bf8(pb[i]);
    __syncthreads();

    for (int s = 0; s < 8; s++) {
        if (s < 7) {
            int k0 = (s + 1) * BK;
            #pragma unroll
            for (int i = 0; i < 4; i++) {
                int m = (tid >> 3) + i * 32;
                int gr = bm + m;
                pa[i] = (gr < N) ? *(const float4*)&A[(size_t)gr * 256 + k0 + ak]
                                 : make_float4(0.f, 0.f, 0.f, 0.f);
            }
            #pragma unroll
            for (int i = 0; i < 2; i++) {
                int k = (tid >> 4) + i * 16;
                pb[i] = *(const float4*)&W[(size_t)(k0 + k) * M + bn + bnq];
            }
        }

        // 2 k-steps of 16
        #pragma unroll
        for (int ks = 0; ks < 2; ks++) {
            int kb = ks * 16;
            uint32_t af[2][4], bf[2][4];
            #pragma unroll
            for (int mt = 0; mt < 2; mt++) {
                int row = wm + mt * 16 + a_r;
                int col = kb + a_c;
                ldsm_x4(af[mt], as_base + (uint32_t)(row * ASTR + col) * 2);
            }
            #pragma unroll
            for (int p = 0; p < 2; p++) {
                int row = kb + (lane & 15);
                int col = wn + p * 16 + (lane >> 4) * 8;
                ldsm_x4_trans(bf[p], ws_base + (uint32_t)(row * BSTR + col) * 2);
            }
            #pragma unroll
            for (int mt = 0; mt < 2; mt++)
                #pragma unroll
                for (int nt = 0; nt < 4; nt++)
                    mma_bf16(acc[mt][nt], af[mt], &bf[nt >> 1][(nt & 1) * 2]);
        }

        __syncthreads();
        if (s < 7) {
            #pragma unroll
            for (int i = 0; i < 4; i++)
                *(uint2*)&As[((tid >> 3) + i * 32) * ASTR + ak] = f4_to_bf8(pa[i]);
            #pragma unroll
            for (int i = 0; i < 2; i++)
                *(uint2*)&Ws[((tid >> 4) + i * 16) * BSTR + bnq] = f4_to_bf8(pb[i]);
            __syncthreads();
        }
    }

    // ---- epilogue ----
    #pragma unroll
    for (int mt = 0; mt < 2; mt++) {
        int r0 = bm + wm + mt * 16 + (lane >> 2);
        #pragma unroll
        for (int nt = 0; nt < 4; nt++) {
            int cb = bn + wn + nt * 8 + (lane & 3) * 2;
            float b0 = bias[cb], b1 = bias[cb + 1];
            float2 lo = make_float2(acc[mt][nt][0] + b0, acc[mt][nt][1] + b1);
            float2 hi = make_float2(acc[mt][nt][2] + b0, acc[mt][nt][3] + b1);
            if (epi == 1) {
                lo.x = 0.5f * lo.x * (1.0f + erff(lo.x * 0.70710678118654752f));
                lo.y = 0.5f * lo.y * (1.0f + erff(lo.y * 0.70710678118654752f));
                hi.x = 0.5f * hi.x * (1.0f + erff(hi.x * 0.70710678118654752f));
                hi.y = 0.5f * hi.y * (1.0f + erff(hi.y * 0.70710678118654752f));
            }
            if (r0 < N)     *(float2*)&C[(size_t)r0 * M + cb] = lo;
            if (r0 + 8 < N) *(float2*)&C[(size_t)(r0 + 8) * M + cb] = hi;
        }
    }
}

// ---------------- edge attention: one warp per edge, float4 + red.v4 ----------------
__global__ void edge_attn(
    const float* __restrict__ Q, const float* __restrict__ KV,
    const int* __restrict__ eq, const int* __restrict__ ek,
    int nE, float* __restrict__ num, float* __restrict__ den)
{
    int warp = (int)(((size_t)blockIdx.x * blockDim.x + threadIdx.x) >> 5);
    int lane = threadIdx.x & 31;
    if (warp >= nE) return;
    int s = eq[warp];
    int t = ek[warp];
    const float4* q4 = (const float4*)(Q + (size_t)s * 256);
    const float4* k4 = (const float4*)(KV + (size_t)t * 512);
    const float4* v4 = k4 + 64;

    float e[2];
    #pragma unroll
    for (int ch = 0; ch < 2; ch++) {
        float4 qq = q4[ch * 32 + lane];
        float4 kk = k4[ch * 32 + lane];
        float p = qq.x * kk.x + qq.y * kk.y + qq.z * kk.z + qq.w * kk.w;
        p += __shfl_xor_sync(0xffffffffu, p, 1);
        p += __shfl_xor_sync(0xffffffffu, p, 2);
        p += __shfl_xor_sync(0xffffffffu, p, 4);
        e[ch] = __expf(p * 0.17677669529663687f);
    }
    #pragma unroll
    for (int ch = 0; ch < 2; ch++) {
        if ((lane & 7) == 0)
            atomicAdd(&den[(size_t)s * NHEAD + ch * 4 + (lane >> 3)], e[ch]);
        float4 vv = v4[ch * 32 + lane];
        red_add_v4(&num[(size_t)s * 256 + ch * 128 + lane * 4],
                   make_float4(e[ch] * vv.x, e[ch] * vv.y, e[ch] * vv.z, e[ch] * vv.w));
    }
}

// ---------------- y = LN(x + num_p/den_p + num_n/den_n) ----------------
__global__ void ln_att(const float* __restrict__ x,
                       const float* __restrict__ np_, const float* __restrict__ dp,
                       const float* __restrict__ nn_, const float* __restrict__ dn,
                       const float* __restrict__ g, const float* __restrict__ b,
                       float* __restrict__ y, int n)
{
    int row = blockIdx.x * (blockDim.x >> 5) + (threadIdx.x >> 5);
    int lane = threadIdx.x & 31;
    if (row >= n) return;
    float vals[8];
    float s = 0.0f;
    #pragma unroll
    for (int i = 0; i < 8; i++) {
        size_t idx = (size_t)row * 256 + i * 32 + lane;
        float a = x[idx];
        float dpi = dp[(size_t)row * NHEAD + i];
        float dni = dn[(size_t)row * NHEAD + i];
        if (dpi > 0.0f) a += np_[idx] / dpi;
        if (dni > 0.0f) a += nn_[idx] / dni;
        vals[i] = a;
        s += a;
    }
    #pragma unroll
    for (int o = 16; o > 0; o >>= 1) s += __shfl_xor_sync(0xffffffffu, s, o);
    float mean = s * (1.0f / 256.0f);
    float v2 = 0.0f;
    #pragma unroll
    for (int i = 0; i < 8; i++) { float d = vals[i] - mean; v2 += d * d; }
    #pragma unroll
    for (int o = 16; o > 0; o >>= 1) v2 += __shfl_xor_sync(0xffffffffu, v2, o);
    float rstd = rsqrtf(v2 * (1.0f / 256.0f) + 1e-5f);
    #pragma unroll
    for (int i = 0; i < 8; i++) {
        int cidx = i * 32 + lane;
        y[(size_t)row * 256 + cidx] = (vals[i] - mean) * rstd * g[cidx] + b[cidx];
    }
}

// ---------------- y = LN(x + a) ----------------
__global__ void ln_add(const float* __restrict__ x, const float* __restrict__ a,
                       const float* __restrict__ g, const float* __restrict__ b,
                       float* __restrict__ y, int n)
{
    int row = blockIdx.x * (blockDim.x >> 5) + (threadIdx.x >> 5);
    int lane = threadIdx.x & 31;
    if (row >= n) return;
    float vals[8];
    float s = 0.0f;
    #pragma unroll
    for (int i = 0; i < 8; i++) {
        size_t idx = (size_t)row * 256 + i * 32 + lane;
        vals[i] = x[idx] + a[idx];
        s += vals[i];
    }
    #pragma unroll
    for (int o = 16; o > 0; o >>= 1) s += __shfl_xor_sync(0xffffffffu, s, o);
    float mean = s * (1.0f / 256.0f);
    float v2 = 0.0f;
    #pragma unroll
    for (int i = 0; i < 8; i++) { float d = vals[i] - mean; v2 += d * d; }
    #pragma unroll
    for (int o = 16; o > 0; o >>= 1) v2 += __shfl_xor_sync(0xffffffffu, v2, o);
    float rstd = rsqrtf(v2 * (1.0f / 256.0f) + 1e-5f);
    #pragma unroll
    for (int i = 0; i < 8; i++) {
        int cidx = i * 32 + lane;
        y[(size_t)row * 256 + cidx] = (vals[i] - mean) * rstd * g[cidx] + b[cidx];
    }
}

static inline void launch_gemm(const float* A, const float* W, const float* bias,
                               float* C, int N, int M, int epi) {
    dim3 grid(M / BN, (N + BM - 1) / BM);
    tgemm<<<grid, 256>>>(A, W, bias, C, N, M, epi);
}

extern "C" void kernel_launch(void* const* d_in, const int* in_sizes, int n_in,
                              void* d_out, int out_size)
{
    const float* v       = (const float*)d_in[0];
    const float* c       = (const float*)d_in[1];
    const int*   adj_pos = (const int*)d_in[2];
    const int*   adj_neg = (const int*)d_in[3];
    const float* Wq      = (const float*)d_in[4];
    const float* bq      = (const float*)d_in[5];
    const float* Wkv     = (const float*)d_in[6];
    const float* bkv     = (const float*)d_in[7];
    const float* fvw1    = (const float*)d_in[8];
    const float* fvb1    = (const float*)d_in[9];
    const float* fvw2    = (const float*)d_in[10];
    const float* fvb2    = (const float*)d_in[11];
    const float* fcw1    = (const float*)d_in[12];
    const float* fcb1    = (const float*)d_in[13];
    const float* fcw2    = (const float*)d_in[14];
    const float* fcb2    = (const float*)d_in[15];
    const float* lavg    = (const float*)d_in[16];
    const float* lavb    = (const float*)d_in[17];
    const float* lfvg    = (const float*)d_in[18];
    const float* lfvb    = (const float*)d_in[19];
    const float* lacg    = (const float*)d_in[20];
    const float* lacb    = (const float*)d_in[21];
    const float* lfcg    = (const float*)d_in[22];
    const float* lfcb    = (const float*)d_in[23];

    int E = in_sizes[2] / 2;

    float* buf;
    cudaGetSymbolAddress((void**)&buf, g_scratch);

    float* qv    = buf + OFF_QV;
    float* kvv   = buf + OFF_KVV;
    float* qc    = buf + OFF_QC;
    float* kvc   = buf + OFF_KVC;
    float* numVp = buf + OFF_NUMVP;
    float* numVn = buf + OFF_NUMVN;
    float* numCp = buf + OFF_NUMCP;
    float* numCn = buf + OFF_NUMCN;
    float* denVp = buf + OFF_DENVP;
    float* denVn = buf + OFF_DENVN;
    float* denCp = buf + OFF_DENCP;
    float* denCn = buf + OFF_DENCN;
    float* v1    = buf + OFF_V1;
    float* c1    = buf + OFF_C1;
    float* hid   = buf + OFF_HID;
    float* tmp   = buf + OFF_TMP;

    float* out_v = (float*)d_out;
    float* out_c = out_v + (size_t)NVAR * DIM;

    cudaMemsetAsync(numVp, 0, (size_t)(OFF_V1 - OFF_NUMVP) * sizeof(float), 0);

    launch_gemm(v, Wq, bq, qv, NVAR, 256, 0);
    launch_gemm(v, Wkv, bkv, kvv, NVAR, 512, 0);
    launch_gemm(c, Wq, bq, qc, NCLS, 256, 0);
    launch_gemm(c, Wkv, bkv, kvc, NCLS, 512, 0);

    int eblocks = (E * 32 + 255) / 256;

    edge_attn<<<eblocks, 256>>>(qv, kvc, adj_pos + E, adj_pos, E, numVp, denVp);
    edge_attn<<<eblocks, 256>>>(qc, kvv, adj_pos, adj_pos + E, E, numCp, denCp);
    edge_attn<<<eblocks, 256>>>(qv, kvc, adj_neg + E, adj_neg, E, numVn, denVn);
    edge_attn<<<eblocks, 256>>>(qc, kvv, adj_neg, adj_neg + E, E, numCn, denCn);

    ln_att<<<(NVAR + 7) / 8, 256>>>(v, numVp, denVp, numVn, denVn, lavg, lavb, v1, NVAR);
    ln_att<<<(NCLS + 7) / 8, 256>>>(c, numCp, denCp, numCn, denCn, lacg, lacb, c1, NCLS);

    launch_gemm(v1, fvw1, fvb1, hid, NVAR, 256, 1);
    launch_gemm(hid, fvw2, fvb2, tmp, NVAR, 256, 0);
    ln_add<<<(NVAR + 7) / 8, 256>>>(v1, tmp, lfvg, lfvb, out_v, NVAR);

    launch_gemm(c1, fcw1, fcb1, hid, NCLS, 256, 1);
    launch_gemm(hid, fcw2, fcb2, tmp, NCLS, 256, 0);
    ln_add<<<(NCLS + 7) / 8, 256>>>(c1, tmp, lfcg, lfcb, out_c, NCLS);
}